// round 17
// baseline (speedup 1.0000x reference)
#include <cuda_runtime.h>

// out[b, f, s] = x[b, 0, s] * w[f, s] + bias[f, s]
// B=128, F=256, S=4096. HBM-write-bound: 512 MiB out.
//
// R17: ALL-REGISTER variant — no smem, no LDS, no syncthreads. x (BT=4) and
// w/bias (FT=2) chunks all live in registers (32 data regs). Steady loop is
// pure FFMA + STG.128: zero memory reads competing with stores in L1/LSU.
// (R14/R16 profiles show L1 at 75-77% — the 1 LDS per 2 STG is ~33% extra
// L1 wavefront traffic. This removes it.)

#define S4     1024        // float4 per row (4096 floats)
#define NFILT  256
#define BATCH  128
#define FT     2           // filters per block (w/bias register-cached)
#define BT     4           // batches per block (x register-cached)
#define CHUNK4 256         // float4 per s-chunk, one per thread

__global__ __launch_bounds__(256, 6) void dense_filter_expand_kernel(
    const float4* __restrict__ x,     // [B, S4]
    const float4* __restrict__ w,     // [F, S4]
    const float4* __restrict__ bias,  // [F, S4]
    float4* __restrict__ out)         // [B, F, S4]
{
    const int t  = threadIdx.x;                // 0..255
    const int sc = blockIdx.x;                 // 0..3    s-chunk
    const int fg = blockIdx.y;                 // 0..127  filter group
    const int bg = blockIdx.z;                 // 0..31   batch group
    const int s4 = sc * CHUNK4 + t;            // float4 index within a row
    const int b0 = bg * BT;
    const int f0 = fg * FT;

    // Preamble: 8 independent LDGs, all batched (full MLP), then no reads.
    float4 xv[BT];
#pragma unroll
    for (int i = 0; i < BT; i++)
        xv[i] = __ldg(&x[(size_t)(b0 + i) * S4 + s4]);

    float4 wv[FT], bv[FT];
#pragma unroll
    for (int ff = 0; ff < FT; ff++) {
        wv[ff] = __ldg(&w[(size_t)(f0 + ff) * S4 + s4]);
        bv[ff] = __ldg(&bias[(size_t)(f0 + ff) * S4 + s4]);
    }

    // Steady state: pure FFMA + streaming stores. Zero memory reads.
#pragma unroll 1
    for (int bb = 0; bb < BT; bb++) {
        float4* obase = out + ((size_t)(b0 + bb) * NFILT + f0) * S4 + s4;
#pragma unroll
        for (int ff = 0; ff < FT; ff++) {
            float4 o;
            o.x = fmaf(xv[bb].x, wv[ff].x, bv[ff].x);
            o.y = fmaf(xv[bb].y, wv[ff].y, bv[ff].y);
            o.z = fmaf(xv[bb].z, wv[ff].z, bv[ff].z);
            o.w = fmaf(xv[bb].w, wv[ff].w, bv[ff].w);
            // Streaming store: output is write-once, never re-read.
            __stcs(obase + (size_t)ff * S4, o);
        }
    }
}

extern "C" void kernel_launch(void* const* d_in, const int* in_sizes, int n_in,
                              void* d_out, int out_size) {
    const float4* x    = (const float4*)d_in[0];   // inputs [128,1,4096]
    const float4* w    = (const float4*)d_in[1];   // w [256,4096]
    const float4* bias = (const float4*)d_in[2];   // b [256,4096]
    float4* out = (float4*)d_out;

    dim3 grid(S4 / CHUNK4, NFILT / FT, BATCH / BT);  // (4, 128, 32) = 16384
    dense_filter_expand_kernel<<<grid, 256>>>(x, w, bias, out);
}